// round 11
// baseline (speedup 1.0000x reference)
#include <cuda_runtime.h>
#include <cuda_bf16.h>
#include <cuda_fp16.h>
#include <math.h>

#define N_NODES 50000
#define N_EDGES 1600000
#define BGRAPH 64
#define AGG_CAP 128

typedef unsigned long long ull;

// ---------------- scratch (device globals; no allocation) ----------------
__device__ __align__(16) float g_h1[N_NODES * 400];
__device__ __align__(16) float g_h2[N_NODES * 20];
__device__ __align__(16) __half g_z1h[N_NODES * 400];
__device__ __align__(16) __half g_z2h[N_NODES * 80];
__device__ __align__(16) float g_W1p[128 * 400];
__device__ __align__(16) float g_W2p[400 * 80];
__device__ float g_s1s[N_NODES * 4];
__device__ float g_s1d[N_NODES * 4];
__device__ float g_s2s[N_NODES * 4];
__device__ float g_s2d[N_NODES * 4];
__device__ int   g_deg[N_NODES];
__device__ int   g_cursor[N_NODES];
__device__ int   g_rowptr[N_NODES + 1];
__device__ int   g_esrc[N_EDGES];
__device__ float g_hg[BGRAPH * 20];

// ---------------- f32x2 helpers ----------------
__device__ __forceinline__ void ffma2(ull& d, ull a, ull b) {
    asm("fma.rn.f32x2 %0, %1, %2, %3;" : "=l"(d) : "l"(a), "l"(b), "l"(d));
}
__device__ __forceinline__ ull rep2(float x) {
    ull r;
    asm("mov.b64 %0, {%1, %1};" : "=l"(r) : "f"(x));
    return r;
}
__device__ __forceinline__ float2 unpack2(ull v) {
    float2 r;
    asm("mov.b64 {%0, %1}, %2;" : "=f"(r.x), "=f"(r.y) : "l"(v));
    return r;
}

// ---------------- zeroing (deg, cursor, scores) ----------------
__global__ void zero_all() {
    int i = blockIdx.x * blockDim.x + threadIdx.x;
    if (i < N_NODES) { g_deg[i] = 0; g_cursor[i] = 0; }
    if (i < N_NODES * 4) {
        g_s1s[i] = 0.f; g_s1d[i] = 0.f;
        g_s2s[i] = 0.f; g_s2d[i] = 0.f;
    }
}

__global__ void hist_kernel(const int* __restrict__ dst) {
    int e = blockIdx.x * blockDim.x + threadIdx.x;
    if (e < N_EDGES) atomicAdd(&g_deg[dst[e]], 1);
}

__global__ void scan_kernel() {
    __shared__ int partial[1024];
    const int PER = (N_NODES + 1023) / 1024;  // 49
    int t = threadIdx.x;
    int s = t * PER;
    int e = min(s + PER, N_NODES);
    int sum = 0;
    for (int i = s; i < e; i++) sum += g_deg[i];
    partial[t] = sum;
    __syncthreads();
    for (int off = 1; off < 1024; off <<= 1) {
        int tmp = partial[t];
        if (t >= off) tmp += partial[t - off];
        __syncthreads();
        partial[t] = tmp;
        __syncthreads();
    }
    int run = partial[t] - sum;  // exclusive offset
    for (int i = s; i < e; i++) { g_rowptr[i] = run; run += g_deg[i]; }
    if (s < N_NODES && e == N_NODES) g_rowptr[N_NODES] = run;
}

__global__ void scatter_kernel(const int* __restrict__ src, const int* __restrict__ dst) {
    int e = blockIdx.x * blockDim.x + threadIdx.x;
    if (e < N_EDGES) {
        int d = dst[e];
        int pos = g_rowptr[d] + atomicAdd(&g_cursor[d], 1);
        g_esrc[pos] = src[e];
    }
}

// ---------------- weight packing: [H,K,DPH] -> [K, H*DPH], both layers ------
__global__ void pack_w(const float* __restrict__ W1, const float* __restrict__ W2) {
    int idx = blockIdx.x * blockDim.x + threadIdx.x;
    if (idx < 4 * 128 * 100) {
        int head = idx / (128 * 100);
        int rem = idx - head * 128 * 100;
        int k = rem / 100, j = rem - k * 100;
        g_W1p[k * 400 + head * 100 + j] = W1[idx];
    }
    if (idx < 4 * 400 * 20) {
        int head = idx / (400 * 20);
        int rem = idx - head * 400 * 20;
        int k = rem / 20, j = rem - k * 20;
        g_W2p[k * 80 + head * 20 + j] = W2[idx];
    }
}

// ---------------- fused GEMM + attn scores + fp16 emit (double-buffered) -----
// C[M,Ncols] = A[M,K] @ Wp[K,Ncols]; emits fp16 z; accumulates per-(row,head)
// attention scores. BM=128, BN=80, BK=16, 256 thr, thread grid 8x32,
// RPT=4 rows x TN=10 cols per thread, f32x2 packed FMA.
template<int BM_, int BN_, int RPT, int TN_>
__global__ void gemm_fused(int layer, const float* __restrict__ Aext,
                           const float* __restrict__ attn,
                           int M, int K, int Ncols, int D) {
    constexpr int BK_ = 16;
    constexpr int AV = BM_ / 64;               // float4 A-loads per thread (2)
    constexpr int BV = (BK_ * BN_) / 256;      // B floats per thread (5)
    __shared__ float Ast[2][BK_][BM_ + 4];     // transposed A tiles
    __shared__ float Bs[2][BK_][BN_];
    __shared__ float s_ss[BM_][4];
    __shared__ float s_sd[BM_][4];

    const float* __restrict__ A = (layer == 1) ? Aext : g_h1;
    const float* __restrict__ Wp = (layer == 1) ? g_W1p : g_W2p;
    __half* __restrict__ Ch = (layer == 1) ? g_z1h : g_z2h;
    float* __restrict__ ss = (layer == 1) ? g_s1s : g_s2s;
    float* __restrict__ sd = (layer == 1) ? g_s1d : g_s2d;

    int tid = threadIdx.x;
    int tx = tid & 7;           // 8 col groups of TN_=10
    int ty = tid >> 3;          // 32 row groups of RPT=4
    int row0 = blockIdx.y * BM_;
    int col0 = blockIdx.x * BN_;

    // zero smem score accumulators
    for (int idx = tid; idx < BM_ * 4; idx += 256) {
        s_ss[idx >> 2][idx & 3] = 0.f;
        s_sd[idx >> 2][idx & 3] = 0.f;
    }

    // precompute staging coordinates (loop-invariant)
    int rA[AV], kA[AV];
    bool vA[AV];
    const float* pA[AV];
#pragma unroll
    for (int v = 0; v < AV; v++) {
        int flat = (tid + v * 256) * 4;
        rA[v] = flat >> 4;
        kA[v] = flat & 15;
        int gr = row0 + rA[v];
        vA[v] = (gr < M);
        pA[v] = A + (size_t)(vA[v] ? gr : 0) * K + kA[v];
    }
    int kB[BV], cB[BV];
    const float* pB[BV];
#pragma unroll
    for (int v = 0; v < BV; v++) {
        int flat = tid + v * 256;
        kB[v] = flat / BN_;
        cB[v] = flat - kB[v] * BN_;
        pB[v] = Wp + (size_t)kB[v] * Ncols + col0 + cB[v];
    }

    ull acc[RPT][TN_ / 2];
#pragma unroll
    for (int i = 0; i < RPT; i++)
#pragma unroll
        for (int p = 0; p < TN_ / 2; p++) acc[i][p] = 0ull;

    float4 aReg[AV];
    float bReg[BV];

    // prologue: tile 0 -> regs -> smem[0]
#pragma unroll
    for (int v = 0; v < AV; v++)
        aReg[v] = vA[v] ? *reinterpret_cast<const float4*>(pA[v])
                        : make_float4(0.f, 0.f, 0.f, 0.f);
#pragma unroll
    for (int v = 0; v < BV; v++) bReg[v] = pB[v][0];
#pragma unroll
    for (int v = 0; v < AV; v++) {
        Ast[0][kA[v] + 0][rA[v]] = aReg[v].x;
        Ast[0][kA[v] + 1][rA[v]] = aReg[v].y;
        Ast[0][kA[v] + 2][rA[v]] = aReg[v].z;
        Ast[0][kA[v] + 3][rA[v]] = aReg[v].w;
    }
#pragma unroll
    for (int v = 0; v < BV; v++) Bs[0][kB[v]][cB[v]] = bReg[v];
    __syncthreads();

    int nT = K / BK_;
    for (int t = 0; t < nT; t++) {
        int cur = t & 1;
        bool more = (t + 1 < nT);
        if (more) {
            int off = (t + 1) * BK_;
#pragma unroll
            for (int v = 0; v < AV; v++)
                aReg[v] = vA[v] ? *reinterpret_cast<const float4*>(pA[v] + off)
                                : make_float4(0.f, 0.f, 0.f, 0.f);
#pragma unroll
            for (int v = 0; v < BV; v++) bReg[v] = pB[v][(size_t)off * Ncols];
        }
#pragma unroll
        for (int kk = 0; kk < BK_; kk++) {
            float4 av = *reinterpret_cast<const float4*>(&Ast[cur][kk][ty * RPT]);
            ull bp[TN_ / 2];
#pragma unroll
            for (int p = 0; p < TN_ / 2; p++)
                bp[p] = *reinterpret_cast<const ull*>(&Bs[cur][kk][tx * TN_ + 2 * p]);
            float ar[RPT] = {av.x, av.y, av.z, av.w};
#pragma unroll
            for (int i = 0; i < RPT; i++) {
                ull ap = rep2(ar[i]);
#pragma unroll
                for (int p = 0; p < TN_ / 2; p++) ffma2(acc[i][p], ap, bp[p]);
            }
        }
        if (more) {
            int nxt = cur ^ 1;
#pragma unroll
            for (int v = 0; v < AV; v++) {
                Ast[nxt][kA[v] + 0][rA[v]] = aReg[v].x;
                Ast[nxt][kA[v] + 1][rA[v]] = aReg[v].y;
                Ast[nxt][kA[v] + 2][rA[v]] = aReg[v].z;
                Ast[nxt][kA[v] + 3][rA[v]] = aReg[v].w;
            }
#pragma unroll
            for (int v = 0; v < BV; v++) Bs[nxt][kB[v]][cB[v]] = bReg[v];
        }
        __syncthreads();
    }

    // ---- epilogue: fp16 store + fused attention scores ----
    // A thread's TN_=10 columns never cross a head boundary (cbase % 10 == 0,
    // boundaries at multiples of D ∈ {100,20} which are multiples of 10).
    int cbase = col0 + tx * TN_;
    int h = cbase / D;
    float wsrc[TN_], wdst[TN_];
#pragma unroll
    for (int j = 0; j < TN_; j++) {
        int cw = cbase + j - h * D;
        wsrc[j] = attn[h * 2 * D + cw];
        wdst[j] = attn[h * 2 * D + D + cw];
    }

#pragma unroll
    for (int i = 0; i < RPT; i++) {
        int r = ty * RPT + i;
        int gr = row0 + r;
        bool valid = (gr < M);
        float f[TN_];
#pragma unroll
        for (int p = 0; p < TN_ / 2; p++) {
            float2 fp = unpack2(acc[i][p]);
            f[2 * p] = fp.x;
            f[2 * p + 1] = fp.y;
        }
        if (valid) {
            __half* dstp = Ch + (size_t)gr * Ncols + cbase;
#pragma unroll
            for (int p = 0; p < TN_ / 2; p++)
                *reinterpret_cast<__half2*>(dstp + 2 * p) =
                    __floats2half2_rn(f[2 * p], f[2 * p + 1]);
        }
        float sls = 0.f, sld = 0.f;
#pragma unroll
        for (int j = 0; j < TN_; j++) {
            sls = fmaf(f[j], wsrc[j], sls);
            sld = fmaf(f[j], wdst[j], sld);
        }
        atomicAdd(&s_ss[r][h], sls);
        atomicAdd(&s_sd[r][h], sld);
    }
    __syncthreads();

    // flush block-local scores to global (only heads this block touches)
    int h0 = col0 / D;
    int h1 = (col0 + BN_ - 1) / D;
    for (int r = tid; r < BM_; r += 256) {
        int gr = row0 + r;
        if (gr >= M) continue;
        for (int hh = h0; hh <= h1; hh++) {
            atomicAdd(&ss[gr * 4 + hh], s_ss[r][hh]);
            atomicAdd(&sd[gr * 4 + hh], s_sd[r][hh]);
        }
    }
}

// ---------------- layer-1 edge softmax + aggregate (block per node, warp per head) --
__global__ void gat_agg1() {
    __shared__ float xsh[4][AGG_CAP];
    __shared__ int esh[AGG_CAP];
    int v = blockIdx.x;
    int i = threadIdx.x >> 5;   // head
    int lane = threadIdx.x & 31;
    int start = g_rowptr[v];
    int end = g_rowptr[v + 1];
    int deg = end - start;
    float sdv = g_s1d[v * 4 + i];

    float m = -1e30f, den = 0.f;
    for (int e = start + lane; e < end; e += 32) {
        int u = g_esrc[e];
        float x = g_s1s[u * 4 + i] + sdv;
        x = (x > 0.f) ? x : 0.01f * x;
        int idx = e - start;
        if (idx < AGG_CAP) {
            xsh[i][idx] = x;
            if (i == 0) esh[idx] = u;
        }
        if (x > m) { den *= __expf(m - x); m = x; }
        den += __expf(x - m);
    }
#pragma unroll
    for (int off = 16; off; off >>= 1) {
        float mo = __shfl_xor_sync(0xffffffffu, m, off);
        float dn = __shfl_xor_sync(0xffffffffu, den, off);
        float mn = fmaxf(m, mo);
        den = den * __expf(m - mn) + dn * __expf(mo - mn);
        m = mn;
    }
    float inv = (den > 0.f) ? (1.0f / den) : 0.f;
    __syncwarp();
    int cached = min(deg, AGG_CAP);
    for (int idx = lane; idx < cached; idx += 32)
        xsh[i][idx] = __expf(xsh[i][idx] - m) * inv;
    __syncthreads();   // esh (head-0 warp) + xsh visible to all

    // aggregate: lanes 0..24 each own 4 channels (100 = 25*4); fp16 gather
    float acc0 = 0.f, acc1 = 0.f, acc2 = 0.f, acc3 = 0.f;
    bool active = (lane < 25);
    for (int idx = 0; idx < deg; idx++) {
        int u;
        float w;
        if (idx < AGG_CAP) {
            u = esh[idx];
            w = xsh[i][idx];
        } else {
            u = g_esrc[start + idx];
            float x = g_s1s[u * 4 + i] + sdv;
            x = (x > 0.f) ? x : 0.01f * x;
            w = __expf(x - m) * inv;
        }
        if (active) {
            const __half2* p = reinterpret_cast<const __half2*>(
                g_z1h + (size_t)u * 400 + i * 100 + lane * 4);
            float2 f0 = __half22float2(p[0]);
            float2 f1 = __half22float2(p[1]);
            acc0 = fmaf(w, f0.x, acc0);
            acc1 = fmaf(w, f0.y, acc1);
            acc2 = fmaf(w, f1.x, acc2);
            acc3 = fmaf(w, f1.y, acc3);
        }
    }
    if (active) {
        float4 r;
        r.x = fmaxf(acc0, 0.f); r.y = fmaxf(acc1, 0.f);
        r.z = fmaxf(acc2, 0.f); r.w = fmaxf(acc3, 0.f);
        *reinterpret_cast<float4*>(g_h1 + (size_t)v * 400 + i * 100 + lane * 4) = r;
    }
}

// ---------------- layer-2 edge softmax + aggregate + head mean + relu ----------------
__global__ void gat_agg2() {
    __shared__ float xsh[4][AGG_CAP];
    __shared__ int esh[AGG_CAP];
    __shared__ float hout[4][20];
    int v = blockIdx.x;
    int i = threadIdx.x >> 5;
    int lane = threadIdx.x & 31;
    int start = g_rowptr[v];
    int end = g_rowptr[v + 1];
    int deg = end - start;
    float sdv = g_s2d[v * 4 + i];

    float m = -1e30f, den = 0.f;
    for (int e = start + lane; e < end; e += 32) {
        int u = g_esrc[e];
        float x = g_s2s[u * 4 + i] + sdv;
        x = (x > 0.f) ? x : 0.01f * x;
        int idx = e - start;
        if (idx < AGG_CAP) {
            xsh[i][idx] = x;
            if (i == 0) esh[idx] = u;
        }
        if (x > m) { den *= __expf(m - x); m = x; }
        den += __expf(x - m);
    }
#pragma unroll
    for (int off = 16; off; off >>= 1) {
        float mo = __shfl_xor_sync(0xffffffffu, m, off);
        float dn = __shfl_xor_sync(0xffffffffu, den, off);
        float mn = fmaxf(m, mo);
        den = den * __expf(m - mn) + dn * __expf(mo - mn);
        m = mn;
    }
    float inv = (den > 0.f) ? (1.0f / den) : 0.f;
    __syncwarp();
    int cached = min(deg, AGG_CAP);
    for (int idx = lane; idx < cached; idx += 32)
        xsh[i][idx] = __expf(xsh[i][idx] - m) * inv;
    __syncthreads();

    float acc = 0.f;
    bool active = (lane < 20);
    for (int idx = 0; idx < deg; idx++) {
        int u;
        float w;
        if (idx < AGG_CAP) {
            u = esh[idx];
            w = xsh[i][idx];
        } else {
            u = g_esrc[start + idx];
            float x = g_s2s[u * 4 + i] + sdv;
            x = (x > 0.f) ? x : 0.01f * x;
            w = __expf(x - m) * inv;
        }
        if (active)
            acc = fmaf(w, __half2float(g_z2h[(size_t)u * 80 + i * 20 + lane]), acc);
    }
    if (active) hout[i][lane] = acc;
    __syncthreads();
    if (threadIdx.x < 20) {
        int c = threadIdx.x;
        float x = 0.25f * (hout[0][c] + hout[1][c] + hout[2][c] + hout[3][c]);
        g_h2[(size_t)v * 20 + c] = fmaxf(x, 0.f);
    }
}

// ---------------- graph mean readout (block per graph, graph_id is sorted) -----------
__global__ void readout_kernel(const int* __restrict__ gid) {
    __shared__ int bnd[2];
    __shared__ float sm[8][20];
    int g = blockIdx.x;
    int t = threadIdx.x;        // 256
    if (t < 2) {
        int target = g + t;
        int lo = 0, hi = N_NODES;
        while (lo < hi) {
            int mid = (lo + hi) >> 1;
            if (gid[mid] < target) lo = mid + 1; else hi = mid;
        }
        bnd[t] = lo;
    }
    __syncthreads();
    int s = bnd[0], e = bnd[1];
    int c = t & 31, rg = t >> 5;  // 8 row groups
    float acc = 0.f;
    if (c < 20)
        for (int r = s + rg; r < e; r += 8) acc += g_h2[(size_t)r * 20 + c];
    if (c < 20) sm[rg][c] = acc;
    __syncthreads();
    if (t < 20) {
        float x = 0.f;
#pragma unroll
        for (int r = 0; r < 8; r++) x += sm[r][t];
        int cnt = e - s;
        g_hg[g * 20 + t] = x / (float)max(cnt, 1);
    }
}

// ---------------- final MLP + BatchNorm (single block) ----------------
__global__ void mlp_kernel(const float* __restrict__ Wf1, const float* __restrict__ bf1,
                           const float* __restrict__ Wf2, const float* __restrict__ bf2,
                           const float* __restrict__ Wf3, const float* __restrict__ bf3,
                           const float* __restrict__ gamma, const float* __restrict__ beta,
                           float* __restrict__ out) {
    __shared__ float hgs[BGRAPH * 20];
    __shared__ float o1[BGRAPH * 128];
    __shared__ float o2[BGRAPH * 32];
    __shared__ float mu[32], rstd[32];
    int t = threadIdx.x;  // 256
    for (int idx = t; idx < BGRAPH * 20; idx += 256) hgs[idx] = g_hg[idx];
    __syncthreads();
    for (int idx = t; idx < BGRAPH * 128; idx += 256) {
        int r = idx >> 7, c = idx & 127;
        float s = bf1[c];
#pragma unroll
        for (int k = 0; k < 20; k++) s = fmaf(hgs[r * 20 + k], Wf1[k * 128 + c], s);
        o1[idx] = fmaxf(s, 0.f);
    }
    __syncthreads();
    for (int idx = t; idx < BGRAPH * 32; idx += 256) {
        int r = idx >> 5, c = idx & 31;
        float s = bf2[c];
        for (int k = 0; k < 128; k++) s = fmaf(o1[r * 128 + k], Wf2[k * 32 + c], s);
        o2[idx] = s;
    }
    __syncthreads();
    if (t < 32) {
        float s = 0.f;
        for (int r = 0; r < BGRAPH; r++) s += o2[r * 32 + t];
        float m_ = s / (float)BGRAPH;
        float v_ = 0.f;
        for (int r = 0; r < BGRAPH; r++) {
            float d = o2[r * 32 + t] - m_;
            v_ = fmaf(d, d, v_);
        }
        v_ /= (float)BGRAPH;
        mu[t] = m_;
        rstd[t] = rsqrtf(v_ + 1e-5f);
    }
    __syncthreads();
    for (int idx = t; idx < BGRAPH * 32; idx += 256) {
        int c = idx & 31;
        float x = gamma[c] * (o2[idx] - mu[c]) * rstd[c] + beta[c];
        o2[idx] = fmaxf(x, 0.f);
    }
    __syncthreads();
    if (t < BGRAPH) {
        float s = bf3[0];
#pragma unroll
        for (int k = 0; k < 32; k++) s = fmaf(o2[t * 32 + k], Wf3[k], s);
        out[t] = s;
    }
}

// ---------------- host launcher ----------------
extern "C" void kernel_launch(void* const* d_in, const int* in_sizes, int n_in,
                              void* d_out, int out_size) {
    const float* feat  = (const float*)d_in[0];
    const int*   src   = (const int*)d_in[1];
    const int*   dst   = (const int*)d_in[2];
    const int*   gid   = (const int*)d_in[3];
    const float* W1    = (const float*)d_in[4];
    const float* a1    = (const float*)d_in[5];
    const float* W2    = (const float*)d_in[6];
    const float* a2    = (const float*)d_in[7];
    const float* Wf1   = (const float*)d_in[8];
    const float* bf1   = (const float*)d_in[9];
    const float* Wf2   = (const float*)d_in[10];
    const float* bf2   = (const float*)d_in[11];
    const float* Wf3   = (const float*)d_in[12];
    const float* bf3   = (const float*)d_in[13];
    const float* gamma = (const float*)d_in[14];
    const float* beta  = (const float*)d_in[15];
    float* out = (float*)d_out;

    // Persistent side stream + events (host objects, created once; identical
    // work on every call — required for graph capture fork/join).
    static cudaStream_t s2 = nullptr;
    static cudaEvent_t evFork = nullptr, evJoin = nullptr;
    if (s2 == nullptr) {
        cudaStreamCreateWithFlags(&s2, cudaStreamNonBlocking);
        cudaEventCreateWithFlags(&evFork, cudaEventDisableTiming);
        cudaEventCreateWithFlags(&evJoin, cudaEventDisableTiming);
    }

    // zeroing must precede both branches (scores + deg/cursor)
    zero_all<<<(N_NODES * 4 + 255) / 256, 256>>>();

    // fork: side stream does weight packing + GEMM1 (compute-bound)
    cudaEventRecord(evFork, 0);
    cudaStreamWaitEvent(s2, evFork, 0);

    {
        pack_w<<<(51200 + 255) / 256, 256, 0, s2>>>(W1, W2);
        dim3 grid(400 / 80, (N_NODES + 127) / 128);
        gemm_fused<128, 80, 4, 10><<<grid, 256, 0, s2>>>(1, feat, a1, N_NODES, 128, 400, 100);
        cudaEventRecord(evJoin, s2);
    }

    // null stream: CSR build (atomic/memory-bound) in parallel
    hist_kernel<<<(N_EDGES + 255) / 256, 256>>>(dst);
    scan_kernel<<<1, 1024>>>();
    scatter_kernel<<<(N_EDGES + 255) / 256, 256>>>(src, dst);

    // join: agg1 needs both CSR and GEMM1 results
    cudaStreamWaitEvent(0, evJoin, 0);
    gat_agg1<<<N_NODES, 128>>>();

    // Layer 2: [50000,400]@[400,80], tile 128x80, fused scores
    {
        dim3 grid(1, (N_NODES + 127) / 128);
        gemm_fused<128, 80, 4, 10><<<grid, 256>>>(2, nullptr, a2, N_NODES, 400, 80, 20);
    }
    gat_agg2<<<N_NODES, 128>>>();

    // Readout + MLP
    readout_kernel<<<BGRAPH, 256>>>(gid);
    mlp_kernel<<<1, 256>>>(Wf1, bf1, Wf2, bf2, Wf3, bf3, gamma, beta, out);
}

// round 12
// speedup vs baseline: 1.2012x; 1.2012x over previous
#include <cuda_runtime.h>
#include <cuda_bf16.h>
#include <cuda_fp16.h>
#include <math.h>

#define N_NODES 50000
#define N_EDGES 1600000
#define BGRAPH 64
#define AGG_CAP 128

typedef unsigned long long ull;

// ---------------- scratch (device globals; no allocation) ----------------
__device__ __align__(16) float g_h1[N_NODES * 400];
__device__ __align__(16) float g_h2[N_NODES * 20];
__device__ __align__(16) __half g_z1h[N_NODES * 400];
__device__ __align__(16) __half g_z2h[N_NODES * 80];
__device__ __align__(16) float g_W1p[128 * 400];
__device__ __align__(16) float g_W2p[400 * 80];
__device__ float g_s1s[N_NODES * 4];
__device__ float g_s1d[N_NODES * 4];
__device__ float g_s2s[N_NODES * 4];
__device__ float g_s2d[N_NODES * 4];
__device__ int   g_deg[N_NODES];
__device__ int   g_cursor[N_NODES];
__device__ int   g_rowptr[N_NODES + 1];
__device__ int   g_esrc[N_EDGES];
__device__ float g_hg[BGRAPH * 20];

// ---------------- f32x2 helpers ----------------
__device__ __forceinline__ void ffma2(ull& d, ull a, ull b) {
    asm("fma.rn.f32x2 %0, %1, %2, %3;" : "=l"(d) : "l"(a), "l"(b), "l"(d));
}
__device__ __forceinline__ ull rep2(float x) {
    ull r;
    asm("mov.b64 %0, {%1, %1};" : "=l"(r) : "f"(x));
    return r;
}
__device__ __forceinline__ float2 unpack2(ull v) {
    float2 r;
    asm("mov.b64 {%0, %1}, %2;" : "=f"(r.x), "=f"(r.y) : "l"(v));
    return r;
}

// ---------------- zeroing (deg, cursor, scores) ----------------
__global__ void zero_all() {
    int i = blockIdx.x * blockDim.x + threadIdx.x;
    if (i < N_NODES) { g_deg[i] = 0; g_cursor[i] = 0; }
    if (i < N_NODES * 4) {
        g_s1s[i] = 0.f; g_s1d[i] = 0.f;
        g_s2s[i] = 0.f; g_s2d[i] = 0.f;
    }
}

__global__ void hist_kernel(const int* __restrict__ dst) {
    int e = blockIdx.x * blockDim.x + threadIdx.x;
    if (e < N_EDGES) atomicAdd(&g_deg[dst[e]], 1);
}

__global__ void scan_kernel() {
    __shared__ int partial[1024];
    const int PER = (N_NODES + 1023) / 1024;  // 49
    int t = threadIdx.x;
    int s = t * PER;
    int e = min(s + PER, N_NODES);
    int sum = 0;
    for (int i = s; i < e; i++) sum += g_deg[i];
    partial[t] = sum;
    __syncthreads();
    for (int off = 1; off < 1024; off <<= 1) {
        int tmp = partial[t];
        if (t >= off) tmp += partial[t - off];
        __syncthreads();
        partial[t] = tmp;
        __syncthreads();
    }
    int run = partial[t] - sum;  // exclusive offset
    for (int i = s; i < e; i++) { g_rowptr[i] = run; run += g_deg[i]; }
    if (s < N_NODES && e == N_NODES) g_rowptr[N_NODES] = run;
}

__global__ void scatter_kernel(const int* __restrict__ src, const int* __restrict__ dst) {
    int e = blockIdx.x * blockDim.x + threadIdx.x;
    if (e < N_EDGES) {
        int d = dst[e];
        int pos = g_rowptr[d] + atomicAdd(&g_cursor[d], 1);
        g_esrc[pos] = src[e];
    }
}

// ---------------- weight packing: [H,K,DPH] -> [K, H*DPH], both layers ------
__global__ void pack_w(const float* __restrict__ W1, const float* __restrict__ W2) {
    int idx = blockIdx.x * blockDim.x + threadIdx.x;
    if (idx < 4 * 128 * 100) {
        int head = idx / (128 * 100);
        int rem = idx - head * 128 * 100;
        int k = rem / 100, j = rem - k * 100;
        g_W1p[k * 400 + head * 100 + j] = W1[idx];
    }
    if (idx < 4 * 400 * 20) {
        int head = idx / (400 * 20);
        int rem = idx - head * 400 * 20;
        int k = rem / 20, j = rem - k * 20;
        g_W2p[k * 80 + head * 20 + j] = W2[idx];
    }
}

// ---------------- fused GEMM + attn scores + fp16 emit ----------------
// (R8 known-good config: simple single-buffer mainloop, f32x2 FMA)
template<int BM_, int BN_, int RPT, int TN_>
__global__ void gemm_fused(int layer, const float* __restrict__ Aext,
                           const float* __restrict__ attn,
                           int M, int K, int Ncols, int D) {
    constexpr int BK_ = 16;
    __shared__ float Ast[BK_][BM_ + 4];   // transposed A tile
    __shared__ float Bs[BK_][BN_];
    __shared__ float s_ss[BM_][4];
    __shared__ float s_sd[BM_][4];

    const float* __restrict__ A = (layer == 1) ? Aext : g_h1;
    const float* __restrict__ Wp = (layer == 1) ? g_W1p : g_W2p;
    __half* __restrict__ Ch = (layer == 1) ? g_z1h : g_z2h;
    float* __restrict__ ss = (layer == 1) ? g_s1s : g_s2s;
    float* __restrict__ sd = (layer == 1) ? g_s1d : g_s2d;

    int tid = threadIdx.x;
    int tx = tid & 7;           // 8 col groups of TN_=10
    int ty = tid >> 3;          // 32 row groups of RPT=4
    int row0 = blockIdx.y * BM_;
    int col0 = blockIdx.x * BN_;

    // zero smem score accumulators
    for (int idx = tid; idx < BM_ * 4; idx += 256) {
        s_ss[idx >> 2][idx & 3] = 0.f;
        s_sd[idx >> 2][idx & 3] = 0.f;
    }

    ull acc[RPT][TN_ / 2];
#pragma unroll
    for (int i = 0; i < RPT; i++)
#pragma unroll
        for (int p = 0; p < TN_ / 2; p++) acc[i][p] = 0ull;

    for (int k0 = 0; k0 < K; k0 += BK_) {
        __syncthreads();
        // stage A (transposed): BM_*16 floats, float4 global loads
#pragma unroll
        for (int v = 0; v < BM_ / 64; v++) {
            int flat = (tid + v * 256) * 4;
            int r = flat >> 4;            // 0..BM_-1
            int kk = flat & 15;
            int gr = row0 + r;
            float4 av = make_float4(0.f, 0.f, 0.f, 0.f);
            if (gr < M)
                av = *reinterpret_cast<const float4*>(&A[(size_t)gr * K + k0 + kk]);
            Ast[kk + 0][r] = av.x;
            Ast[kk + 1][r] = av.y;
            Ast[kk + 2][r] = av.z;
            Ast[kk + 3][r] = av.w;
        }
        // stage B: 16*80 = 1280 floats, 5 per thread
#pragma unroll
        for (int v = 0; v < (BK_ * BN_) / 256; v++) {
            int flat = tid + v * 256;
            int kk = flat / BN_;
            int c = flat - kk * BN_;
            Bs[kk][c] = Wp[(size_t)(k0 + kk) * Ncols + col0 + c];
        }
        __syncthreads();
#pragma unroll
        for (int kk = 0; kk < BK_; kk++) {
            float4 av = *reinterpret_cast<const float4*>(&Ast[kk][ty * RPT]);
            ull bp[TN_ / 2];
#pragma unroll
            for (int p = 0; p < TN_ / 2; p++)
                bp[p] = *reinterpret_cast<const ull*>(&Bs[kk][tx * TN_ + 2 * p]);
            float ar[RPT] = {av.x, av.y, av.z, av.w};
#pragma unroll
            for (int i = 0; i < RPT; i++) {
                ull ap = rep2(ar[i]);
#pragma unroll
                for (int p = 0; p < TN_ / 2; p++) ffma2(acc[i][p], ap, bp[p]);
            }
        }
    }

    // ---- epilogue: fp16 store + fused attention scores ----
    int cbase = col0 + tx * TN_;
    int h = cbase / D;
    float wsrc[TN_], wdst[TN_];
#pragma unroll
    for (int j = 0; j < TN_; j++) {
        int cw = cbase + j - h * D;
        wsrc[j] = attn[h * 2 * D + cw];
        wdst[j] = attn[h * 2 * D + D + cw];
    }

#pragma unroll
    for (int i = 0; i < RPT; i++) {
        int r = ty * RPT + i;
        int gr = row0 + r;
        bool valid = (gr < M);
        float f[TN_];
#pragma unroll
        for (int p = 0; p < TN_ / 2; p++) {
            float2 fp = unpack2(acc[i][p]);
            f[2 * p] = fp.x;
            f[2 * p + 1] = fp.y;
        }
        if (valid) {
            __half* dstp = Ch + (size_t)gr * Ncols + cbase;
#pragma unroll
            for (int p = 0; p < TN_ / 2; p++)
                *reinterpret_cast<__half2*>(dstp + 2 * p) =
                    __floats2half2_rn(f[2 * p], f[2 * p + 1]);
        }
        float sls = 0.f, sld = 0.f;
#pragma unroll
        for (int j = 0; j < TN_; j++) {
            sls = fmaf(f[j], wsrc[j], sls);
            sld = fmaf(f[j], wdst[j], sld);
        }
        atomicAdd(&s_ss[r][h], sls);
        atomicAdd(&s_sd[r][h], sld);
    }
    __syncthreads();

    // flush block-local scores to global (only heads this block touches)
    int h0 = col0 / D;
    int h1 = (col0 + BN_ - 1) / D;
    for (int r = tid; r < BM_; r += 256) {
        int gr = row0 + r;
        if (gr >= M) continue;
        for (int hh = h0; hh <= h1; hh++) {
            atomicAdd(&ss[gr * 4 + hh], s_ss[r][hh]);
            atomicAdd(&sd[gr * 4 + hh], s_sd[r][hh]);
        }
    }
}

// ---------------- layer-1 edge softmax + aggregate (block per node, warp per head) --
__global__ void gat_agg1() {
    __shared__ float xsh[4][AGG_CAP];
    int v = blockIdx.x;
    int i = threadIdx.x >> 5;   // head
    int lane = threadIdx.x & 31;
    int start = g_rowptr[v];
    int end = g_rowptr[v + 1];
    int deg = end - start;
    float sdv = g_s1d[v * 4 + i];

    float m = -1e30f, den = 0.f;
    for (int e = start + lane; e < end; e += 32) {
        int u = g_esrc[e];
        float x = g_s1s[u * 4 + i] + sdv;
        x = (x > 0.f) ? x : 0.01f * x;
        int idx = e - start;
        if (idx < AGG_CAP) xsh[i][idx] = x;
        if (x > m) { den *= __expf(m - x); m = x; }
        den += __expf(x - m);
    }
#pragma unroll
    for (int off = 16; off; off >>= 1) {
        float mo = __shfl_xor_sync(0xffffffffu, m, off);
        float dn = __shfl_xor_sync(0xffffffffu, den, off);
        float mn = fmaxf(m, mo);
        den = den * __expf(m - mn) + dn * __expf(mo - mn);
        m = mn;
    }
    float inv = (den > 0.f) ? (1.0f / den) : 0.f;
    __syncwarp();
    int cached = min(deg, AGG_CAP);
    for (int idx = lane; idx < cached; idx += 32)
        xsh[i][idx] = __expf(xsh[i][idx] - m) * inv;
    __syncwarp();

    // aggregate: lanes 0..24 own 4 channels each; unroll x2 with independent
    // accumulator sets to double outstanding gathers per warp (MLP).
    float a0 = 0.f, a1 = 0.f, a2 = 0.f, a3 = 0.f;
    float b0 = 0.f, b1 = 0.f, b2 = 0.f, b3 = 0.f;
    bool active = (lane < 25);
    int idx = 0;
    for (; idx + 2 <= deg; idx += 2) {
        int u0 = g_esrc[start + idx];
        int u1 = g_esrc[start + idx + 1];
        float w0, w1;
        if (idx < AGG_CAP) {
            w0 = xsh[i][idx];
        } else {
            float x = g_s1s[u0 * 4 + i] + sdv;
            x = (x > 0.f) ? x : 0.01f * x;
            w0 = __expf(x - m) * inv;
        }
        if (idx + 1 < AGG_CAP) {
            w1 = xsh[i][idx + 1];
        } else {
            float x = g_s1s[u1 * 4 + i] + sdv;
            x = (x > 0.f) ? x : 0.01f * x;
            w1 = __expf(x - m) * inv;
        }
        if (active) {
            const __half2* p0 = reinterpret_cast<const __half2*>(
                g_z1h + (size_t)u0 * 400 + i * 100 + lane * 4);
            const __half2* p1 = reinterpret_cast<const __half2*>(
                g_z1h + (size_t)u1 * 400 + i * 100 + lane * 4);
            float2 f00 = __half22float2(p0[0]);
            float2 f01 = __half22float2(p0[1]);
            float2 f10 = __half22float2(p1[0]);
            float2 f11 = __half22float2(p1[1]);
            a0 = fmaf(w0, f00.x, a0);
            a1 = fmaf(w0, f00.y, a1);
            a2 = fmaf(w0, f01.x, a2);
            a3 = fmaf(w0, f01.y, a3);
            b0 = fmaf(w1, f10.x, b0);
            b1 = fmaf(w1, f10.y, b1);
            b2 = fmaf(w1, f11.x, b2);
            b3 = fmaf(w1, f11.y, b3);
        }
    }
    if (idx < deg) {
        int u = g_esrc[start + idx];
        float w;
        if (idx < AGG_CAP) {
            w = xsh[i][idx];
        } else {
            float x = g_s1s[u * 4 + i] + sdv;
            x = (x > 0.f) ? x : 0.01f * x;
            w = __expf(x - m) * inv;
        }
        if (active) {
            const __half2* p = reinterpret_cast<const __half2*>(
                g_z1h + (size_t)u * 400 + i * 100 + lane * 4);
            float2 f0 = __half22float2(p[0]);
            float2 f1 = __half22float2(p[1]);
            a0 = fmaf(w, f0.x, a0);
            a1 = fmaf(w, f0.y, a1);
            a2 = fmaf(w, f1.x, a2);
            a3 = fmaf(w, f1.y, a3);
        }
    }
    if (active) {
        float4 r;
        r.x = fmaxf(a0 + b0, 0.f);
        r.y = fmaxf(a1 + b1, 0.f);
        r.z = fmaxf(a2 + b2, 0.f);
        r.w = fmaxf(a3 + b3, 0.f);
        *reinterpret_cast<float4*>(g_h1 + (size_t)v * 400 + i * 100 + lane * 4) = r;
    }
}

// ---------------- layer-2 edge softmax + aggregate + head mean + relu ----------------
__global__ void gat_agg2() {
    __shared__ float xsh[4][AGG_CAP];
    __shared__ float hout[4][20];
    int v = blockIdx.x;
    int i = threadIdx.x >> 5;
    int lane = threadIdx.x & 31;
    int start = g_rowptr[v];
    int end = g_rowptr[v + 1];
    int deg = end - start;
    float sdv = g_s2d[v * 4 + i];

    float m = -1e30f, den = 0.f;
    for (int e = start + lane; e < end; e += 32) {
        int u = g_esrc[e];
        float x = g_s2s[u * 4 + i] + sdv;
        x = (x > 0.f) ? x : 0.01f * x;
        int idx = e - start;
        if (idx < AGG_CAP) xsh[i][idx] = x;
        if (x > m) { den *= __expf(m - x); m = x; }
        den += __expf(x - m);
    }
#pragma unroll
    for (int off = 16; off; off >>= 1) {
        float mo = __shfl_xor_sync(0xffffffffu, m, off);
        float dn = __shfl_xor_sync(0xffffffffu, den, off);
        float mn = fmaxf(m, mo);
        den = den * __expf(m - mn) + dn * __expf(mo - mn);
        m = mn;
    }
    float inv = (den > 0.f) ? (1.0f / den) : 0.f;
    __syncwarp();
    int cached = min(deg, AGG_CAP);
    for (int idx = lane; idx < cached; idx += 32)
        xsh[i][idx] = __expf(xsh[i][idx] - m) * inv;
    __syncwarp();

    float accA = 0.f, accB = 0.f;
    bool active = (lane < 20);
    int idx = 0;
    for (; idx + 2 <= deg; idx += 2) {
        int u0 = g_esrc[start + idx];
        int u1 = g_esrc[start + idx + 1];
        float w0, w1;
        if (idx < AGG_CAP) {
            w0 = xsh[i][idx];
        } else {
            float x = g_s2s[u0 * 4 + i] + sdv;
            x = (x > 0.f) ? x : 0.01f * x;
            w0 = __expf(x - m) * inv;
        }
        if (idx + 1 < AGG_CAP) {
            w1 = xsh[i][idx + 1];
        } else {
            float x = g_s2s[u1 * 4 + i] + sdv;
            x = (x > 0.f) ? x : 0.01f * x;
            w1 = __expf(x - m) * inv;
        }
        if (active) {
            accA = fmaf(w0, __half2float(g_z2h[(size_t)u0 * 80 + i * 20 + lane]), accA);
            accB = fmaf(w1, __half2float(g_z2h[(size_t)u1 * 80 + i * 20 + lane]), accB);
        }
    }
    if (idx < deg) {
        int u = g_esrc[start + idx];
        float w;
        if (idx < AGG_CAP) {
            w = xsh[i][idx];
        } else {
            float x = g_s2s[u * 4 + i] + sdv;
            x = (x > 0.f) ? x : 0.01f * x;
            w = __expf(x - m) * inv;
        }
        if (active)
            accA = fmaf(w, __half2float(g_z2h[(size_t)u * 80 + i * 20 + lane]), accA);
    }
    if (active) hout[i][lane] = accA + accB;
    __syncthreads();
    if (threadIdx.x < 20) {
        int c = threadIdx.x;
        float x = 0.25f * (hout[0][c] + hout[1][c] + hout[2][c] + hout[3][c]);
        g_h2[(size_t)v * 20 + c] = fmaxf(x, 0.f);
    }
}

// ---------------- graph mean readout (block per graph, graph_id is sorted) -----------
__global__ void readout_kernel(const int* __restrict__ gid) {
    __shared__ int bnd[2];
    __shared__ float sm[8][20];
    int g = blockIdx.x;
    int t = threadIdx.x;        // 256
    if (t < 2) {
        int target = g + t;
        int lo = 0, hi = N_NODES;
        while (lo < hi) {
            int mid = (lo + hi) >> 1;
            if (gid[mid] < target) lo = mid + 1; else hi = mid;
        }
        bnd[t] = lo;
    }
    __syncthreads();
    int s = bnd[0], e = bnd[1];
    int c = t & 31, rg = t >> 5;  // 8 row groups
    float acc = 0.f;
    if (c < 20)
        for (int r = s + rg; r < e; r += 8) acc += g_h2[(size_t)r * 20 + c];
    if (c < 20) sm[rg][c] = acc;
    __syncthreads();
    if (t < 20) {
        float x = 0.f;
#pragma unroll
        for (int r = 0; r < 8; r++) x += sm[r][t];
        int cnt = e - s;
        g_hg[g * 20 + t] = x / (float)max(cnt, 1);
    }
}

// ---------------- final MLP + BatchNorm (single block) ----------------
__global__ void mlp_kernel(const float* __restrict__ Wf1, const float* __restrict__ bf1,
                           const float* __restrict__ Wf2, const float* __restrict__ bf2,
                           const float* __restrict__ Wf3, const float* __restrict__ bf3,
                           const float* __restrict__ gamma, const float* __restrict__ beta,
                           float* __restrict__ out) {
    __shared__ float hgs[BGRAPH * 20];
    __shared__ float o1[BGRAPH * 128];
    __shared__ float o2[BGRAPH * 32];
    __shared__ float mu[32], rstd[32];
    int t = threadIdx.x;  // 256
    for (int idx = t; idx < BGRAPH * 20; idx += 256) hgs[idx] = g_hg[idx];
    __syncthreads();
    for (int idx = t; idx < BGRAPH * 128; idx += 256) {
        int r = idx >> 7, c = idx & 127;
        float s = bf1[c];
#pragma unroll
        for (int k = 0; k < 20; k++) s = fmaf(hgs[r * 20 + k], Wf1[k * 128 + c], s);
        o1[idx] = fmaxf(s, 0.f);
    }
    __syncthreads();
    for (int idx = t; idx < BGRAPH * 32; idx += 256) {
        int r = idx >> 5, c = idx & 31;
        float s = bf2[c];
        for (int k = 0; k < 128; k++) s = fmaf(o1[r * 128 + k], Wf2[k * 32 + c], s);
        o2[idx] = s;
    }
    __syncthreads();
    if (t < 32) {
        float s = 0.f;
        for (int r = 0; r < BGRAPH; r++) s += o2[r * 32 + t];
        float m_ = s / (float)BGRAPH;
        float v_ = 0.f;
        for (int r = 0; r < BGRAPH; r++) {
            float d = o2[r * 32 + t] - m_;
            v_ = fmaf(d, d, v_);
        }
        v_ /= (float)BGRAPH;
        mu[t] = m_;
        rstd[t] = rsqrtf(v_ + 1e-5f);
    }
    __syncthreads();
    for (int idx = t; idx < BGRAPH * 32; idx += 256) {
        int c = idx & 31;
        float x = gamma[c] * (o2[idx] - mu[c]) * rstd[c] + beta[c];
        o2[idx] = fmaxf(x, 0.f);
    }
    __syncthreads();
    if (t < BGRAPH) {
        float s = bf3[0];
#pragma unroll
        for (int k = 0; k < 32; k++) s = fmaf(o2[t * 32 + k], Wf3[k], s);
        out[t] = s;
    }
}

// ---------------- host launcher ----------------
extern "C" void kernel_launch(void* const* d_in, const int* in_sizes, int n_in,
                              void* d_out, int out_size) {
    const float* feat  = (const float*)d_in[0];
    const int*   src   = (const int*)d_in[1];
    const int*   dst   = (const int*)d_in[2];
    const int*   gid   = (const int*)d_in[3];
    const float* W1    = (const float*)d_in[4];
    const float* a1    = (const float*)d_in[5];
    const float* W2    = (const float*)d_in[6];
    const float* a2    = (const float*)d_in[7];
    const float* Wf1   = (const float*)d_in[8];
    const float* bf1   = (const float*)d_in[9];
    const float* Wf2   = (const float*)d_in[10];
    const float* bf2   = (const float*)d_in[11];
    const float* Wf3   = (const float*)d_in[12];
    const float* bf3   = (const float*)d_in[13];
    const float* gamma = (const float*)d_in[14];
    const float* beta  = (const float*)d_in[15];
    float* out = (float*)d_out;

    // Persistent side stream + events (host objects, created once; identical
    // work on every call — required for graph capture fork/join).
    static cudaStream_t s2 = nullptr;
    static cudaEvent_t evFork = nullptr, evJoin = nullptr;
    if (s2 == nullptr) {
        cudaStreamCreateWithFlags(&s2, cudaStreamNonBlocking);
        cudaEventCreateWithFlags(&evFork, cudaEventDisableTiming);
        cudaEventCreateWithFlags(&evJoin, cudaEventDisableTiming);
    }

    // zeroing must precede both branches (scores + deg/cursor)
    zero_all<<<(N_NODES * 4 + 255) / 256, 256>>>();

    // fork: side stream does weight packing + GEMM1 (compute-bound)
    cudaEventRecord(evFork, 0);
    cudaStreamWaitEvent(s2, evFork, 0);

    {
        pack_w<<<(51200 + 255) / 256, 256, 0, s2>>>(W1, W2);
        dim3 grid(400 / 80, (N_NODES + 127) / 128);
        gemm_fused<128, 80, 4, 10><<<grid, 256, 0, s2>>>(1, feat, a1, N_NODES, 128, 400, 100);
        cudaEventRecord(evJoin, s2);
    }

    // null stream: CSR build (atomic/memory-bound) in parallel
    hist_kernel<<<(N_EDGES + 255) / 256, 256>>>(dst);
    scan_kernel<<<1, 1024>>>();
    scatter_kernel<<<(N_EDGES + 255) / 256, 256>>>(src, dst);

    // join: agg1 needs both CSR and GEMM1 results
    cudaStreamWaitEvent(0, evJoin, 0);
    gat_agg1<<<N_NODES, 128>>>();

    // Layer 2: [50000,400]@[400,80], tile 128x80, fused scores
    {
        dim3 grid(1, (N_NODES + 127) / 128);
        gemm_fused<128, 80, 4, 10><<<grid, 256>>>(2, nullptr, a2, N_NODES, 400, 80, 20);
    }
    gat_agg2<<<N_NODES, 128>>>();

    // Readout + MLP
    readout_kernel<<<BGRAPH, 256>>>(gid);
    mlp_kernel<<<1, 256>>>(Wf1, bf1, Wf2, bf2, Wf3, bf3, gamma, beta, out);
}

// round 13
// speedup vs baseline: 1.2405x; 1.0327x over previous
#include <cuda_runtime.h>
#include <cuda_bf16.h>
#include <cuda_fp16.h>
#include <math.h>

#define N_NODES 50000
#define N_EDGES 1600000
#define BGRAPH 64
#define AGG_CAP 128

typedef unsigned long long ull;

// ---------------- scratch (device globals; no allocation) ----------------
__device__ __align__(16) float g_h1[N_NODES * 400];
__device__ __align__(16) float g_h2[N_NODES * 20];
__device__ __align__(16) __half g_z1h[N_NODES * 400];
__device__ __align__(16) __half g_z2h[N_NODES * 80];
__device__ __align__(16) float g_W1p[128 * 400];
__device__ __align__(16) float g_W2p[400 * 80];
__device__ float g_s1s[N_NODES * 4];
__device__ float g_s1d[N_NODES * 4];
__device__ float g_s2s[N_NODES * 4];
__device__ float g_s2d[N_NODES * 4];
__device__ int   g_deg[N_NODES];
__device__ int   g_cursor[N_NODES];
__device__ int   g_rowptr[N_NODES + 1];
__device__ int   g_esrc[N_EDGES];
__device__ float g_hg[BGRAPH * 20];

// ---------------- f32x2 helpers ----------------
__device__ __forceinline__ void ffma2(ull& d, ull a, ull b) {
    asm("fma.rn.f32x2 %0, %1, %2, %3;" : "=l"(d) : "l"(a), "l"(b), "l"(d));
}
__device__ __forceinline__ ull rep2(float x) {
    ull r;
    asm("mov.b64 %0, {%1, %1};" : "=l"(r) : "f"(x));
    return r;
}
__device__ __forceinline__ float2 unpack2(ull v) {
    float2 r;
    asm("mov.b64 {%0, %1}, %2;" : "=f"(r.x), "=f"(r.y) : "l"(v));
    return r;
}

// ---------------- zeroing (deg, cursor, scores) ----------------
__global__ void zero_all() {
    int i = blockIdx.x * blockDim.x + threadIdx.x;
    if (i < N_NODES) { g_deg[i] = 0; g_cursor[i] = 0; }
    if (i < N_NODES * 4) {
        g_s1s[i] = 0.f; g_s1d[i] = 0.f;
        g_s2s[i] = 0.f; g_s2d[i] = 0.f;
    }
}

__global__ void hist_kernel(const int* __restrict__ dst) {
    int e = blockIdx.x * blockDim.x + threadIdx.x;
    if (e < N_EDGES) atomicAdd(&g_deg[dst[e]], 1);
}

__global__ void scan_kernel() {
    __shared__ int partial[1024];
    const int PER = (N_NODES + 1023) / 1024;  // 49
    int t = threadIdx.x;
    int s = t * PER;
    int e = min(s + PER, N_NODES);
    int sum = 0;
    for (int i = s; i < e; i++) sum += g_deg[i];
    partial[t] = sum;
    __syncthreads();
    for (int off = 1; off < 1024; off <<= 1) {
        int tmp = partial[t];
        if (t >= off) tmp += partial[t - off];
        __syncthreads();
        partial[t] = tmp;
        __syncthreads();
    }
    int run = partial[t] - sum;  // exclusive offset
    for (int i = s; i < e; i++) { g_rowptr[i] = run; run += g_deg[i]; }
    if (s < N_NODES && e == N_NODES) g_rowptr[N_NODES] = run;
}

__global__ void scatter_kernel(const int* __restrict__ src, const int* __restrict__ dst) {
    int e = blockIdx.x * blockDim.x + threadIdx.x;
    if (e < N_EDGES) {
        int d = dst[e];
        int pos = g_rowptr[d] + atomicAdd(&g_cursor[d], 1);
        g_esrc[pos] = src[e];
    }
}

// ---------------- weight packing: [H,K,DPH] -> [K, H*DPH], both layers ------
__global__ void pack_w(const float* __restrict__ W1, const float* __restrict__ W2) {
    int idx = blockIdx.x * blockDim.x + threadIdx.x;
    if (idx < 4 * 128 * 100) {
        int head = idx / (128 * 100);
        int rem = idx - head * 128 * 100;
        int k = rem / 100, j = rem - k * 100;
        g_W1p[k * 400 + head * 100 + j] = W1[idx];
    }
    if (idx < 4 * 400 * 20) {
        int head = idx / (400 * 20);
        int rem = idx - head * 400 * 20;
        int k = rem / 20, j = rem - k * 20;
        g_W2p[k * 80 + head * 20 + j] = W2[idx];
    }
}

// ---------------- fused GEMM + attn scores + fp16 emit ----------------
// (R8/R12 known-good config: simple single-buffer mainloop, f32x2 FMA)
template<int BM_, int BN_, int RPT, int TN_>
__global__ void gemm_fused(int layer, const float* __restrict__ Aext,
                           const float* __restrict__ attn,
                           int M, int K, int Ncols, int D) {
    constexpr int BK_ = 16;
    __shared__ float Ast[BK_][BM_ + 4];   // transposed A tile
    __shared__ float Bs[BK_][BN_];
    __shared__ float s_ss[BM_][4];
    __shared__ float s_sd[BM_][4];

    const float* __restrict__ A = (layer == 1) ? Aext : g_h1;
    const float* __restrict__ Wp = (layer == 1) ? g_W1p : g_W2p;
    __half* __restrict__ Ch = (layer == 1) ? g_z1h : g_z2h;
    float* __restrict__ ss = (layer == 1) ? g_s1s : g_s2s;
    float* __restrict__ sd = (layer == 1) ? g_s1d : g_s2d;

    int tid = threadIdx.x;
    int tx = tid & 7;           // 8 col groups of TN_=10
    int ty = tid >> 3;          // 32 row groups of RPT=4
    int row0 = blockIdx.y * BM_;
    int col0 = blockIdx.x * BN_;

    // zero smem score accumulators
    for (int idx = tid; idx < BM_ * 4; idx += 256) {
        s_ss[idx >> 2][idx & 3] = 0.f;
        s_sd[idx >> 2][idx & 3] = 0.f;
    }

    ull acc[RPT][TN_ / 2];
#pragma unroll
    for (int i = 0; i < RPT; i++)
#pragma unroll
        for (int p = 0; p < TN_ / 2; p++) acc[i][p] = 0ull;

    for (int k0 = 0; k0 < K; k0 += BK_) {
        __syncthreads();
        // stage A (transposed): BM_*16 floats, float4 global loads
#pragma unroll
        for (int v = 0; v < BM_ / 64; v++) {
            int flat = (tid + v * 256) * 4;
            int r = flat >> 4;            // 0..BM_-1
            int kk = flat & 15;
            int gr = row0 + r;
            float4 av = make_float4(0.f, 0.f, 0.f, 0.f);
            if (gr < M)
                av = *reinterpret_cast<const float4*>(&A[(size_t)gr * K + k0 + kk]);
            Ast[kk + 0][r] = av.x;
            Ast[kk + 1][r] = av.y;
            Ast[kk + 2][r] = av.z;
            Ast[kk + 3][r] = av.w;
        }
        // stage B: 16*80 = 1280 floats, 5 per thread
#pragma unroll
        for (int v = 0; v < (BK_ * BN_) / 256; v++) {
            int flat = tid + v * 256;
            int kk = flat / BN_;
            int c = flat - kk * BN_;
            Bs[kk][c] = Wp[(size_t)(k0 + kk) * Ncols + col0 + c];
        }
        __syncthreads();
#pragma unroll
        for (int kk = 0; kk < BK_; kk++) {
            float4 av = *reinterpret_cast<const float4*>(&Ast[kk][ty * RPT]);
            ull bp[TN_ / 2];
#pragma unroll
            for (int p = 0; p < TN_ / 2; p++)
                bp[p] = *reinterpret_cast<const ull*>(&Bs[kk][tx * TN_ + 2 * p]);
            float ar[RPT] = {av.x, av.y, av.z, av.w};
#pragma unroll
            for (int i = 0; i < RPT; i++) {
                ull ap = rep2(ar[i]);
#pragma unroll
                for (int p = 0; p < TN_ / 2; p++) ffma2(acc[i][p], ap, bp[p]);
            }
        }
    }

    // ---- epilogue: fp16 store + fused attention scores ----
    int cbase = col0 + tx * TN_;
    int h = cbase / D;
    float wsrc[TN_], wdst[TN_];
#pragma unroll
    for (int j = 0; j < TN_; j++) {
        int cw = cbase + j - h * D;
        wsrc[j] = attn[h * 2 * D + cw];
        wdst[j] = attn[h * 2 * D + D + cw];
    }

#pragma unroll
    for (int i = 0; i < RPT; i++) {
        int r = ty * RPT + i;
        int gr = row0 + r;
        bool valid = (gr < M);
        float f[TN_];
#pragma unroll
        for (int p = 0; p < TN_ / 2; p++) {
            float2 fp = unpack2(acc[i][p]);
            f[2 * p] = fp.x;
            f[2 * p + 1] = fp.y;
        }
        if (valid) {
            __half* dstp = Ch + (size_t)gr * Ncols + cbase;
#pragma unroll
            for (int p = 0; p < TN_ / 2; p++)
                *reinterpret_cast<__half2*>(dstp + 2 * p) =
                    __floats2half2_rn(f[2 * p], f[2 * p + 1]);
        }
        float sls = 0.f, sld = 0.f;
#pragma unroll
        for (int j = 0; j < TN_; j++) {
            sls = fmaf(f[j], wsrc[j], sls);
            sld = fmaf(f[j], wdst[j], sld);
        }
        atomicAdd(&s_ss[r][h], sls);
        atomicAdd(&s_sd[r][h], sld);
    }
    __syncthreads();

    // flush block-local scores to global (only heads this block touches)
    int h0 = col0 / D;
    int h1 = (col0 + BN_ - 1) / D;
    for (int r = tid; r < BM_; r += 256) {
        int gr = row0 + r;
        if (gr >= M) continue;
        for (int hh = h0; hh <= h1; hh++) {
            atomicAdd(&ss[gr * 4 + hh], s_ss[r][hh]);
            atomicAdd(&sd[gr * 4 + hh], s_sd[r][hh]);
        }
    }
}

// ---------------- layer-1 edge softmax + aggregate (block per node, warp per head) --
// aggregate loop unrolled x4 with independent accumulator sets (gather MLP=4)
__global__ void gat_agg1() {
    __shared__ float xsh[4][AGG_CAP];
    int v = blockIdx.x;
    int i = threadIdx.x >> 5;   // head
    int lane = threadIdx.x & 31;
    int start = g_rowptr[v];
    int end = g_rowptr[v + 1];
    int deg = end - start;
    float sdv = g_s1d[v * 4 + i];

    float m = -1e30f, den = 0.f;
    for (int e = start + lane; e < end; e += 32) {
        int u = g_esrc[e];
        float x = g_s1s[u * 4 + i] + sdv;
        x = (x > 0.f) ? x : 0.01f * x;
        int idx = e - start;
        if (idx < AGG_CAP) xsh[i][idx] = x;
        if (x > m) { den *= __expf(m - x); m = x; }
        den += __expf(x - m);
    }
#pragma unroll
    for (int off = 16; off; off >>= 1) {
        float mo = __shfl_xor_sync(0xffffffffu, m, off);
        float dn = __shfl_xor_sync(0xffffffffu, den, off);
        float mn = fmaxf(m, mo);
        den = den * __expf(m - mn) + dn * __expf(mo - mn);
        m = mn;
    }
    float inv = (den > 0.f) ? (1.0f / den) : 0.f;
    __syncwarp();
    int cached = min(deg, AGG_CAP);
    for (int idx = lane; idx < cached; idx += 32)
        xsh[i][idx] = __expf(xsh[i][idx] - m) * inv;
    __syncwarp();

    float A0 = 0.f, A1 = 0.f, A2 = 0.f, A3 = 0.f;
    float B0 = 0.f, B1 = 0.f, B2 = 0.f, B3 = 0.f;
    float C0 = 0.f, C1 = 0.f, C2 = 0.f, C3 = 0.f;
    float D0 = 0.f, D1 = 0.f, D2 = 0.f, D3 = 0.f;
    bool active = (lane < 25);
    int idx = 0;
    for (; idx + 4 <= deg; idx += 4) {
        int u0 = g_esrc[start + idx];
        int u1 = g_esrc[start + idx + 1];
        int u2 = g_esrc[start + idx + 2];
        int u3 = g_esrc[start + idx + 3];
        float w0, w1, w2, w3;
        if (idx + 3 < AGG_CAP) {
            w0 = xsh[i][idx];
            w1 = xsh[i][idx + 1];
            w2 = xsh[i][idx + 2];
            w3 = xsh[i][idx + 3];
        } else {
            float x0 = g_s1s[u0 * 4 + i] + sdv; x0 = (x0 > 0.f) ? x0 : 0.01f * x0;
            float x1 = g_s1s[u1 * 4 + i] + sdv; x1 = (x1 > 0.f) ? x1 : 0.01f * x1;
            float x2 = g_s1s[u2 * 4 + i] + sdv; x2 = (x2 > 0.f) ? x2 : 0.01f * x2;
            float x3 = g_s1s[u3 * 4 + i] + sdv; x3 = (x3 > 0.f) ? x3 : 0.01f * x3;
            w0 = __expf(x0 - m) * inv;
            w1 = __expf(x1 - m) * inv;
            w2 = __expf(x2 - m) * inv;
            w3 = __expf(x3 - m) * inv;
        }
        if (active) {
            const __half2* p0 = reinterpret_cast<const __half2*>(
                g_z1h + (size_t)u0 * 400 + i * 100 + lane * 4);
            const __half2* p1 = reinterpret_cast<const __half2*>(
                g_z1h + (size_t)u1 * 400 + i * 100 + lane * 4);
            const __half2* p2 = reinterpret_cast<const __half2*>(
                g_z1h + (size_t)u2 * 400 + i * 100 + lane * 4);
            const __half2* p3 = reinterpret_cast<const __half2*>(
                g_z1h + (size_t)u3 * 400 + i * 100 + lane * 4);
            float2 f00 = __half22float2(p0[0]), f01 = __half22float2(p0[1]);
            float2 f10 = __half22float2(p1[0]), f11 = __half22float2(p1[1]);
            float2 f20 = __half22float2(p2[0]), f21 = __half22float2(p2[1]);
            float2 f30 = __half22float2(p3[0]), f31 = __half22float2(p3[1]);
            A0 = fmaf(w0, f00.x, A0); A1 = fmaf(w0, f00.y, A1);
            A2 = fmaf(w0, f01.x, A2); A3 = fmaf(w0, f01.y, A3);
            B0 = fmaf(w1, f10.x, B0); B1 = fmaf(w1, f10.y, B1);
            B2 = fmaf(w1, f11.x, B2); B3 = fmaf(w1, f11.y, B3);
            C0 = fmaf(w2, f20.x, C0); C1 = fmaf(w2, f20.y, C1);
            C2 = fmaf(w2, f21.x, C2); C3 = fmaf(w2, f21.y, C3);
            D0 = fmaf(w3, f30.x, D0); D1 = fmaf(w3, f30.y, D1);
            D2 = fmaf(w3, f31.x, D2); D3 = fmaf(w3, f31.y, D3);
        }
    }
    for (; idx < deg; idx++) {
        int u = g_esrc[start + idx];
        float w;
        if (idx < AGG_CAP) {
            w = xsh[i][idx];
        } else {
            float x = g_s1s[u * 4 + i] + sdv;
            x = (x > 0.f) ? x : 0.01f * x;
            w = __expf(x - m) * inv;
        }
        if (active) {
            const __half2* p = reinterpret_cast<const __half2*>(
                g_z1h + (size_t)u * 400 + i * 100 + lane * 4);
            float2 f0 = __half22float2(p[0]);
            float2 f1 = __half22float2(p[1]);
            A0 = fmaf(w, f0.x, A0); A1 = fmaf(w, f0.y, A1);
            A2 = fmaf(w, f1.x, A2); A3 = fmaf(w, f1.y, A3);
        }
    }
    if (active) {
        float4 r;
        r.x = fmaxf((A0 + B0) + (C0 + D0), 0.f);
        r.y = fmaxf((A1 + B1) + (C1 + D1), 0.f);
        r.z = fmaxf((A2 + B2) + (C2 + D2), 0.f);
        r.w = fmaxf((A3 + B3) + (C3 + D3), 0.f);
        *reinterpret_cast<float4*>(g_h1 + (size_t)v * 400 + i * 100 + lane * 4) = r;
    }
}

// ---------------- layer-2 edge softmax + aggregate + head mean + relu ----------------
__global__ void gat_agg2() {
    __shared__ float xsh[4][AGG_CAP];
    __shared__ float hout[4][20];
    int v = blockIdx.x;
    int i = threadIdx.x >> 5;
    int lane = threadIdx.x & 31;
    int start = g_rowptr[v];
    int end = g_rowptr[v + 1];
    int deg = end - start;
    float sdv = g_s2d[v * 4 + i];

    float m = -1e30f, den = 0.f;
    for (int e = start + lane; e < end; e += 32) {
        int u = g_esrc[e];
        float x = g_s2s[u * 4 + i] + sdv;
        x = (x > 0.f) ? x : 0.01f * x;
        int idx = e - start;
        if (idx < AGG_CAP) xsh[i][idx] = x;
        if (x > m) { den *= __expf(m - x); m = x; }
        den += __expf(x - m);
    }
#pragma unroll
    for (int off = 16; off; off >>= 1) {
        float mo = __shfl_xor_sync(0xffffffffu, m, off);
        float dn = __shfl_xor_sync(0xffffffffu, den, off);
        float mn = fmaxf(m, mo);
        den = den * __expf(m - mn) + dn * __expf(mo - mn);
        m = mn;
    }
    float inv = (den > 0.f) ? (1.0f / den) : 0.f;
    __syncwarp();
    int cached = min(deg, AGG_CAP);
    for (int idx = lane; idx < cached; idx += 32)
        xsh[i][idx] = __expf(xsh[i][idx] - m) * inv;
    __syncwarp();

    float accA = 0.f, accB = 0.f, accC = 0.f, accD = 0.f;
    bool active = (lane < 20);
    int idx = 0;
    for (; idx + 4 <= deg; idx += 4) {
        int u0 = g_esrc[start + idx];
        int u1 = g_esrc[start + idx + 1];
        int u2 = g_esrc[start + idx + 2];
        int u3 = g_esrc[start + idx + 3];
        float w0, w1, w2, w3;
        if (idx + 3 < AGG_CAP) {
            w0 = xsh[i][idx];
            w1 = xsh[i][idx + 1];
            w2 = xsh[i][idx + 2];
            w3 = xsh[i][idx + 3];
        } else {
            float x0 = g_s2s[u0 * 4 + i] + sdv; x0 = (x0 > 0.f) ? x0 : 0.01f * x0;
            float x1 = g_s2s[u1 * 4 + i] + sdv; x1 = (x1 > 0.f) ? x1 : 0.01f * x1;
            float x2 = g_s2s[u2 * 4 + i] + sdv; x2 = (x2 > 0.f) ? x2 : 0.01f * x2;
            float x3 = g_s2s[u3 * 4 + i] + sdv; x3 = (x3 > 0.f) ? x3 : 0.01f * x3;
            w0 = __expf(x0 - m) * inv;
            w1 = __expf(x1 - m) * inv;
            w2 = __expf(x2 - m) * inv;
            w3 = __expf(x3 - m) * inv;
        }
        if (active) {
            accA = fmaf(w0, __half2float(g_z2h[(size_t)u0 * 80 + i * 20 + lane]), accA);
            accB = fmaf(w1, __half2float(g_z2h[(size_t)u1 * 80 + i * 20 + lane]), accB);
            accC = fmaf(w2, __half2float(g_z2h[(size_t)u2 * 80 + i * 20 + lane]), accC);
            accD = fmaf(w3, __half2float(g_z2h[(size_t)u3 * 80 + i * 20 + lane]), accD);
        }
    }
    for (; idx < deg; idx++) {
        int u = g_esrc[start + idx];
        float w;
        if (idx < AGG_CAP) {
            w = xsh[i][idx];
        } else {
            float x = g_s2s[u * 4 + i] + sdv;
            x = (x > 0.f) ? x : 0.01f * x;
            w = __expf(x - m) * inv;
        }
        if (active)
            accA = fmaf(w, __half2float(g_z2h[(size_t)u * 80 + i * 20 + lane]), accA);
    }
    if (active) hout[i][lane] = (accA + accB) + (accC + accD);
    __syncthreads();
    if (threadIdx.x < 20) {
        int c = threadIdx.x;
        float x = 0.25f * (hout[0][c] + hout[1][c] + hout[2][c] + hout[3][c]);
        g_h2[(size_t)v * 20 + c] = fmaxf(x, 0.f);
    }
}

// ---------------- graph mean readout (block per graph, graph_id is sorted) -----------
__global__ void readout_kernel(const int* __restrict__ gid) {
    __shared__ int bnd[2];
    __shared__ float sm[8][20];
    int g = blockIdx.x;
    int t = threadIdx.x;        // 256
    if (t < 2) {
        int target = g + t;
        int lo = 0, hi = N_NODES;
        while (lo < hi) {
            int mid = (lo + hi) >> 1;
            if (gid[mid] < target) lo = mid + 1; else hi = mid;
        }
        bnd[t] = lo;
    }
    __syncthreads();
    int s = bnd[0], e = bnd[1];
    int c = t & 31, rg = t >> 5;  // 8 row groups
    float acc = 0.f;
    if (c < 20)
        for (int r = s + rg; r < e; r += 8) acc += g_h2[(size_t)r * 20 + c];
    if (c < 20) sm[rg][c] = acc;
    __syncthreads();
    if (t < 20) {
        float x = 0.f;
#pragma unroll
        for (int r = 0; r < 8; r++) x += sm[r][t];
        int cnt = e - s;
        g_hg[g * 20 + t] = x / (float)max(cnt, 1);
    }
}

// ---------------- final MLP + BatchNorm (single block) ----------------
__global__ void mlp_kernel(const float* __restrict__ Wf1, const float* __restrict__ bf1,
                           const float* __restrict__ Wf2, const float* __restrict__ bf2,
                           const float* __restrict__ Wf3, const float* __restrict__ bf3,
                           const float* __restrict__ gamma, const float* __restrict__ beta,
                           float* __restrict__ out) {
    __shared__ float hgs[BGRAPH * 20];
    __shared__ float o1[BGRAPH * 128];
    __shared__ float o2[BGRAPH * 32];
    __shared__ float mu[32], rstd[32];
    int t = threadIdx.x;  // 256
    for (int idx = t; idx < BGRAPH * 20; idx += 256) hgs[idx] = g_hg[idx];
    __syncthreads();
    for (int idx = t; idx < BGRAPH * 128; idx += 256) {
        int r = idx >> 7, c = idx & 127;
        float s = bf1[c];
#pragma unroll
        for (int k = 0; k < 20; k++) s = fmaf(hgs[r * 20 + k], Wf1[k * 128 + c], s);
        o1[idx] = fmaxf(s, 0.f);
    }
    __syncthreads();
    for (int idx = t; idx < BGRAPH * 32; idx += 256) {
        int r = idx >> 5, c = idx & 31;
        float s = bf2[c];
        for (int k = 0; k < 128; k++) s = fmaf(o1[r * 128 + k], Wf2[k * 32 + c], s);
        o2[idx] = s;
    }
    __syncthreads();
    if (t < 32) {
        float s = 0.f;
        for (int r = 0; r < BGRAPH; r++) s += o2[r * 32 + t];
        float m_ = s / (float)BGRAPH;
        float v_ = 0.f;
        for (int r = 0; r < BGRAPH; r++) {
            float d = o2[r * 32 + t] - m_;
            v_ = fmaf(d, d, v_);
        }
        v_ /= (float)BGRAPH;
        mu[t] = m_;
        rstd[t] = rsqrtf(v_ + 1e-5f);
    }
    __syncthreads();
    for (int idx = t; idx < BGRAPH * 32; idx += 256) {
        int c = idx & 31;
        float x = gamma[c] * (o2[idx] - mu[c]) * rstd[c] + beta[c];
        o2[idx] = fmaxf(x, 0.f);
    }
    __syncthreads();
    if (t < BGRAPH) {
        float s = bf3[0];
#pragma unroll
        for (int k = 0; k < 32; k++) s = fmaf(o2[t * 32 + k], Wf3[k], s);
        out[t] = s;
    }
}

// ---------------- host launcher ----------------
extern "C" void kernel_launch(void* const* d_in, const int* in_sizes, int n_in,
                              void* d_out, int out_size) {
    const float* feat  = (const float*)d_in[0];
    const int*   src   = (const int*)d_in[1];
    const int*   dst   = (const int*)d_in[2];
    const int*   gid   = (const int*)d_in[3];
    const float* W1    = (const float*)d_in[4];
    const float* a1    = (const float*)d_in[5];
    const float* W2    = (const float*)d_in[6];
    const float* a2    = (const float*)d_in[7];
    const float* Wf1   = (const float*)d_in[8];
    const float* bf1   = (const float*)d_in[9];
    const float* Wf2   = (const float*)d_in[10];
    const float* bf2   = (const float*)d_in[11];
    const float* Wf3   = (const float*)d_in[12];
    const float* bf3   = (const float*)d_in[13];
    const float* gamma = (const float*)d_in[14];
    const float* beta  = (const float*)d_in[15];
    float* out = (float*)d_out;

    // Persistent side stream + events (host objects, created once; identical
    // work on every call — required for graph capture fork/join).
    static cudaStream_t s2 = nullptr;
    static cudaEvent_t evFork = nullptr, evJoin = nullptr;
    if (s2 == nullptr) {
        cudaStreamCreateWithFlags(&s2, cudaStreamNonBlocking);
        cudaEventCreateWithFlags(&evFork, cudaEventDisableTiming);
        cudaEventCreateWithFlags(&evJoin, cudaEventDisableTiming);
    }

    // zeroing must precede both branches (scores + deg/cursor)
    zero_all<<<(N_NODES * 4 + 255) / 256, 256>>>();

    // fork: side stream does weight packing + GEMM1 (compute-bound)
    cudaEventRecord(evFork, 0);
    cudaStreamWaitEvent(s2, evFork, 0);

    {
        pack_w<<<(51200 + 255) / 256, 256, 0, s2>>>(W1, W2);
        dim3 grid(400 / 80, (N_NODES + 127) / 128);
        gemm_fused<128, 80, 4, 10><<<grid, 256, 0, s2>>>(1, feat, a1, N_NODES, 128, 400, 100);
        cudaEventRecord(evJoin, s2);
    }

    // null stream: CSR build (atomic/memory-bound) in parallel
    hist_kernel<<<(N_EDGES + 255) / 256, 256>>>(dst);
    scan_kernel<<<1, 1024>>>();
    scatter_kernel<<<(N_EDGES + 255) / 256, 256>>>(src, dst);

    // join: agg1 needs both CSR and GEMM1 results
    cudaStreamWaitEvent(0, evJoin, 0);
    gat_agg1<<<N_NODES, 128>>>();

    // Layer 2: [50000,400]@[400,80], tile 128x80, fused scores
    {
        dim3 grid(1, (N_NODES + 127) / 128);
        gemm_fused<128, 80, 4, 10><<<grid, 256>>>(2, nullptr, a2, N_NODES, 400, 80, 20);
    }
    gat_agg2<<<N_NODES, 128>>>();

    // Readout + MLP
    readout_kernel<<<BGRAPH, 256>>>(gid);
    mlp_kernel<<<1, 256>>>(Wf1, bf1, Wf2, bf2, Wf3, bf3, gamma, beta, out);
}